// round 6
// baseline (speedup 1.0000x reference)
#include <cuda_runtime.h>
#include <cuda_fp16.h>

// cumulative_hazard: per-row tiny RNN (11 steps, 8 neurons, 9 inputs) + 3 dense layers.
// R4: occupancy 2->3 blocks/SM (reg cap 85); y-gap values packed to f16x2 to cut
//     register pressure. 2 rows/thread, fp32x2 packed FMA, weights in shared.

typedef unsigned long long u64;

#define NTHREADS 256

__device__ __forceinline__ u64 pack2(float lo, float hi) {
    u64 d; asm("mov.b64 %0, {%1, %2};" : "=l"(d) : "f"(lo), "f"(hi)); return d;
}
__device__ __forceinline__ void unpack2(u64 v, float& lo, float& hi) {
    asm("mov.b64 {%0, %1}, %2;" : "=f"(lo), "=f"(hi) : "l"(v));
}
__device__ __forceinline__ u64 ffma2(u64 a, u64 b, u64 c) {
    u64 d; asm("fma.rn.f32x2 %0, %1, %2, %3;" : "=l"(d) : "l"(a), "l"(b), "l"(c)); return d;
}

// f16x2 pack of two f32 (single F2FP.PACK)
__device__ __forceinline__ unsigned packh2(float a, float b) {
    unsigned r; asm("cvt.rn.f16x2.f32 %0, %2, %1;" : "=r"(r) : "f"(a), "f"(b));
    return r;  // lo=a, hi=b
}
// unpack f16x2 -> f32x2 pair
__device__ __forceinline__ u64 h2_to_f2(unsigned h) {
    __half2 v = *reinterpret_cast<__half2*>(&h);
    return pack2(__low2float(v), __high2float(v));
}

// fast RNN tanh: f16x2, single MUFU per pair
__device__ __forceinline__ u64 tanh2_h(u64 v) {
    float a, b; unpack2(v, a, b);
    unsigned hr = packh2(a, b);
    asm("tanh.approx.f16x2 %0, %0;" : "+r"(hr));
    return h2_to_f2(hr);
}

// accurate f32 HW tanh for the output-side layers
__device__ __forceinline__ u64 tanh2_f(u64 v) {
    float a, b; unpack2(v, a, b);
    asm("tanh.approx.f32 %0, %0;" : "+f"(a));
    asm("tanh.approx.f32 %0, %0;" : "+f"(b));
    return pack2(a, b);
}

// numerically stable softplus (only 2 per thread; precise path)
__device__ __forceinline__ float softplus_out(float x) {
    float ax = fabsf(x);
    float l = log1pf(__expf(-ax));
    return x > 0.0f ? x + l : l;
}
__device__ __forceinline__ float sp_precise(float x) {  // weight preprocessing
    float ax = fabsf(x);
    float l = log1pf(expf(-ax));
    return x > 0.0f ? x + l : l;
}

__global__ __launch_bounds__(NTHREADS, 3)
void hazard_kernel(const float* __restrict__ Y,     // [N,16]
                   const float* __restrict__ tau,   // [N,1]
                   const float* __restrict__ f1W,   // [8,9]
                   const float* __restrict__ f1b,   // [8]
                   const float* __restrict__ ftW,   // [8,1]
                   const float* __restrict__ ftb,   // [8]
                   const float* __restrict__ f20W,  // [8,8]
                   const float* __restrict__ f20b,  // [8]
                   const float* __restrict__ f21W,  // [8,8]
                   const float* __restrict__ f21b,  // [8]
                   const float* __restrict__ f22W,  // [1,8]
                   const float* __restrict__ f22b,  // [1]
                   float* __restrict__ out,         // [N]
                   int npairs)
{
    __shared__ u64 sW1[72], sB1[8];
    __shared__ u64 sW20[64], sB20[8], sTW[8];
    __shared__ u64 sW21[64], sB21[8];
    __shared__ u64 sW22[8], sB22;

    const int t = threadIdx.x;
    // ---- per-block weight preprocessing (softplus folded, duplicated pairs) ----
    if (t < 72)        { float v = f1W[t];                         sW1[t] = pack2(v, v); }
    else if (t < 80)   { int i = t - 72;  float v = f1b[i];        sB1[i] = pack2(v, v); }
    else if (t < 144)  { int i = t - 80;  float v = f20W[i];       sW20[i] = pack2(v, v); }
    else if (t < 152)  { int i = t - 144; float v = f20b[i] + sp_precise(ftb[i]); sB20[i] = pack2(v, v); }
    else if (t < 160)  { int i = t - 152; float v = sp_precise(ftW[i]);  sTW[i] = pack2(v, v); }
    else if (t < 224)  { int i = t - 160; float v = sp_precise(f21W[i]); sW21[i] = pack2(v, v); }
    else if (t < 232)  { int i = t - 224; float v = sp_precise(f21b[i]); sB21[i] = pack2(v, v); }
    else if (t < 240)  { int i = t - 232; float v = sp_precise(f22W[i]); sW22[i] = pack2(v, v); }
    else if (t == 240) { float v = sp_precise(f22b[0]);            sB22 = pack2(v, v); }
    __syncthreads();

    const int gid = blockIdx.x * NTHREADS + t;
    if (gid >= npairs) return;

    const long long r0 = (long long)gid * 2;

    // ---- load 2 rows of Y_seq (32 floats, 128B contiguous per thread) ----
    const float4* yp = (const float4*)(Y + r0 * 16);
    float4 q0 = yp[0], q1 = yp[1], q2 = yp[2], q3 = yp[3];  // row r0
    float4 p0 = yp[4], p1 = yp[5], p2 = yp[6], p3 = yp[7];  // row r0+1

    float ra[16] = { q0.x,q0.y,q0.z,q0.w, q1.x,q1.y,q1.z,q1.w,
                     q2.x,q2.y,q2.z,q2.w, q3.x,q3.y,q3.z,q3.w };
    float rb[16] = { p0.x,p0.y,p0.z,p0.w, p1.x,p1.y,p1.z,p1.w,
                     p2.x,p2.y,p2.z,p2.w, p3.x,p3.y,p3.z,p3.w };

    // y[j] = log(Y[:,4+j] - Y[:,3+j] + 0.1), j = 0..10 — stored f16x2 (reg relief)
    unsigned yh[11];
#pragma unroll
    for (int j = 0; j < 11; j++) {
        float d0 = __logf(ra[4 + j] - ra[3 + j] + 0.1f);
        float d1 = __logf(rb[4 + j] - rb[3 + j] + 0.1f);
        yh[j] = packh2(d0, d1);
    }

    // ---- RNN: flow = tanh([flow, y_j] @ f1W^T + f1b), 11 steps ----
    // step 0: flow == 0, so acc = y0 * W[:,8] + b
    u64 flow[8];
    {
        u64 y0 = h2_to_f2(yh[0]);
#pragma unroll
        for (int i = 0; i < 8; i++)
            flow[i] = tanh2_h(ffma2(y0, sW1[i * 9 + 8], sB1[i]));
    }

#pragma unroll
    for (int j = 1; j < 11; j++) {
        u64 yj = h2_to_f2(yh[j]);
        u64 acc[8];
#pragma unroll
        for (int i = 0; i < 8; i++) {
            u64 a1 = sB1[i];
#pragma unroll
            for (int k = 0; k < 8; k++) a1 = ffma2(flow[k], sW1[i * 9 + k], a1);
            a1 = ffma2(yj, sW1[i * 9 + 8], a1);
            acc[i] = a1;
        }
#pragma unroll
        for (int i = 0; i < 8; i++) flow[i] = tanh2_h(acc[i]);
    }

    // ---- f2 layer 0: tanh(flow @ W20^T + b20' + tau * sp(Wtau)^T) ----
    u64 taup;
    {
        float2 tv = *(const float2*)(tau + r0);
        taup = pack2(tv.x, tv.y);
    }
    u64 g[8];
#pragma unroll
    for (int i = 0; i < 8; i++) {
        u64 a1 = sB20[i];
        a1 = ffma2(taup, sTW[i], a1);
#pragma unroll
        for (int k = 0; k < 8; k++) a1 = ffma2(flow[k], sW20[i * 8 + k], a1);
        g[i] = tanh2_f(a1);
    }

    // ---- f2 layer 1: tanh(g @ sp(W21)^T + sp(b21)) ----
    u64 h[8];
#pragma unroll
    for (int i = 0; i < 8; i++) {
        u64 a1 = sB21[i];
#pragma unroll
        for (int k = 0; k < 8; k++) a1 = ffma2(g[k], sW21[i * 8 + k], a1);
        h[i] = tanh2_f(a1);
    }

    // ---- output: softplus(h @ sp(W22)^T + sp(b22)) ----
    u64 o = sB22;
#pragma unroll
    for (int k = 0; k < 8; k++) o = ffma2(h[k], sW22[k], o);

    float o0, o1; unpack2(o, o0, o1);
    float2 res;
    res.x = softplus_out(o0);
    res.y = softplus_out(o1);
    *(float2*)(out + r0) = res;
}

extern "C" void kernel_launch(void* const* d_in, const int* in_sizes, int n_in,
                              void* d_out, int out_size)
{
    const float* Y    = (const float*)d_in[0];
    const float* tau  = (const float*)d_in[1];
    const float* f1W  = (const float*)d_in[2];
    const float* f1b  = (const float*)d_in[3];
    const float* ftW  = (const float*)d_in[4];
    const float* ftb  = (const float*)d_in[5];
    const float* f20W = (const float*)d_in[6];
    const float* f20b = (const float*)d_in[7];
    const float* f21W = (const float*)d_in[8];
    const float* f21b = (const float*)d_in[9];
    const float* f22W = (const float*)d_in[10];
    const float* f22b = (const float*)d_in[11];
    float* out = (float*)d_out;

    int npairs = out_size / 2;  // 2M threads, 2 rows each
    int blocks = (npairs + NTHREADS - 1) / NTHREADS;
    hazard_kernel<<<blocks, NTHREADS>>>(Y, tau, f1W, f1b, ftW, ftb,
                                        f20W, f20b, f21W, f21b, f22W, f22b,
                                        out, npairs);
}

// round 8
// speedup vs baseline: 2.6729x; 2.6729x over previous
#include <cuda_runtime.h>
#include <cuda_fp16.h>

// cumulative_hazard: per-row tiny RNN (11 steps, 8 neurons, 9 inputs) + 3 dense layers.
// R6: RNN fully in f16x2 (HFMA2) with weights RESIDENT IN REGISTERS (80 regs as
//     half2(w,w)) -> kills ~720 LDS + ~600 cvt per thread. tanh.approx.f16x2
//     directly on accumulators. f2 layers stay f32x2 + shared + f32 tanh.
//     2 blocks/SM (128-reg point; R4 proved 85-reg cap spills catastrophically).

typedef unsigned long long u64;

#define NTHREADS 256

__device__ __forceinline__ u64 pack2(float lo, float hi) {
    u64 d; asm("mov.b64 %0, {%1, %2};" : "=l"(d) : "f"(lo), "f"(hi)); return d;
}
__device__ __forceinline__ void unpack2(u64 v, float& lo, float& hi) {
    asm("mov.b64 {%0, %1}, %2;" : "=f"(lo), "=f"(hi) : "l"(v));
}
__device__ __forceinline__ u64 ffma2(u64 a, u64 b, u64 c) {
    u64 d; asm("fma.rn.f32x2 %0, %1, %2, %3;" : "=l"(d) : "l"(a), "l"(b), "l"(c)); return d;
}

// f16x2 pack of two f32
__device__ __forceinline__ __half2 packh2(float a, float b) {
    return __floats2half2_rn(a, b);
}
// half2 -> f32x2 pair
__device__ __forceinline__ u64 h2_to_f2(__half2 v) {
    return pack2(__low2float(v), __high2float(v));
}

// HW tanh on f16x2, in place (1 MUFU per pair, no cvts)
__device__ __forceinline__ __half2 tanh_h2(__half2 v) {
    unsigned r = *reinterpret_cast<unsigned*>(&v);
    asm("tanh.approx.f16x2 %0, %0;" : "+r"(r));
    return *reinterpret_cast<__half2*>(&r);
}

// accurate f32 HW tanh for the output-side layers
__device__ __forceinline__ u64 tanh2_f(u64 v) {
    float a, b; unpack2(v, a, b);
    asm("tanh.approx.f32 %0, %0;" : "+f"(a));
    asm("tanh.approx.f32 %0, %0;" : "+f"(b));
    return pack2(a, b);
}

// numerically stable softplus (only 2 per thread; precise path)
__device__ __forceinline__ float softplus_out(float x) {
    float ax = fabsf(x);
    float l = log1pf(__expf(-ax));
    return x > 0.0f ? x + l : l;
}
__device__ __forceinline__ float sp_precise(float x) {  // weight preprocessing
    float ax = fabsf(x);
    float l = log1pf(expf(-ax));
    return x > 0.0f ? x + l : l;
}

__global__ __launch_bounds__(NTHREADS, 2)
void hazard_kernel(const float* __restrict__ Y,     // [N,16]
                   const float* __restrict__ tau,   // [N,1]
                   const float* __restrict__ f1W,   // [8,9]
                   const float* __restrict__ f1b,   // [8]
                   const float* __restrict__ ftW,   // [8,1]
                   const float* __restrict__ ftb,   // [8]
                   const float* __restrict__ f20W,  // [8,8]
                   const float* __restrict__ f20b,  // [8]
                   const float* __restrict__ f21W,  // [8,8]
                   const float* __restrict__ f21b,  // [8]
                   const float* __restrict__ f22W,  // [1,8]
                   const float* __restrict__ f22b,  // [1]
                   float* __restrict__ out,         // [N]
                   int npairs)
{
    // RNN weights as half2(w,w); f2 weights as f32x2(w,w)
    __shared__ __half2 sW1h[72], sB1h[8];
    __shared__ u64 sW20[64], sB20[8], sTW[8];
    __shared__ u64 sW21[64], sB21[8];
    __shared__ u64 sW22[8], sB22;

    const int t = threadIdx.x;
    // ---- per-block weight preprocessing (softplus folded, duplicated pairs) ----
    if (t < 72)        { float v = f1W[t];                         sW1h[t] = packh2(v, v); }
    else if (t < 80)   { int i = t - 72;  float v = f1b[i];        sB1h[i] = packh2(v, v); }
    else if (t < 144)  { int i = t - 80;  float v = f20W[i];       sW20[i] = pack2(v, v); }
    else if (t < 152)  { int i = t - 144; float v = f20b[i] + sp_precise(ftb[i]); sB20[i] = pack2(v, v); }
    else if (t < 160)  { int i = t - 152; float v = sp_precise(ftW[i]);  sTW[i] = pack2(v, v); }
    else if (t < 224)  { int i = t - 160; float v = sp_precise(f21W[i]); sW21[i] = pack2(v, v); }
    else if (t < 232)  { int i = t - 224; float v = sp_precise(f21b[i]); sB21[i] = pack2(v, v); }
    else if (t < 240)  { int i = t - 232; float v = sp_precise(f22W[i]); sW22[i] = pack2(v, v); }
    else if (t == 240) { float v = sp_precise(f22b[0]);            sB22 = pack2(v, v); }
    __syncthreads();

    const int gid = blockIdx.x * NTHREADS + t;
    if (gid >= npairs) return;

    const long long r0 = (long long)gid * 2;

    // ---- load 2 rows of Y_seq (32 floats, 128B contiguous per thread) ----
    const float4* yp = (const float4*)(Y + r0 * 16);
    float4 q0 = yp[0], q1 = yp[1], q2 = yp[2], q3 = yp[3];  // row r0
    float4 p0 = yp[4], p1 = yp[5], p2 = yp[6], p3 = yp[7];  // row r0+1

    float ra[16] = { q0.x,q0.y,q0.z,q0.w, q1.x,q1.y,q1.z,q1.w,
                     q2.x,q2.y,q2.z,q2.w, q3.x,q3.y,q3.z,q3.w };
    float rb[16] = { p0.x,p0.y,p0.z,p0.w, p1.x,p1.y,p1.z,p1.w,
                     p2.x,p2.y,p2.z,p2.w, p3.x,p3.y,p3.z,p3.w };

    // y[j] = log(Y[:,4+j] - Y[:,3+j] + 0.1), j = 0..10 — f16x2 (lane = row)
    __half2 y[11];
#pragma unroll
    for (int j = 0; j < 11; j++) {
        float d0 = __logf(ra[4 + j] - ra[3 + j] + 0.1f);
        float d1 = __logf(rb[4 + j] - rb[3 + j] + 0.1f);
        y[j] = packh2(d0, d1);
    }

    // ---- pull RNN weights into REGISTERS (80 regs, broadcast LDS once) ----
    __half2 w1[72], b1[8];
#pragma unroll
    for (int i = 0; i < 72; i++) w1[i] = sW1h[i];
#pragma unroll
    for (int i = 0; i < 8; i++)  b1[i] = sB1h[i];

    // ---- RNN in f16x2: flow = tanh([flow, y_j] @ W^T + b), 11 steps ----
    // step 0: flow == 0  ->  acc = y0 * W[:,8] + b
    __half2 flow[8];
#pragma unroll
    for (int i = 0; i < 8; i++)
        flow[i] = tanh_h2(__hfma2(y[0], w1[i * 9 + 8], b1[i]));

#pragma unroll
    for (int j = 1; j < 11; j++) {
        __half2 acc[8];
#pragma unroll
        for (int i = 0; i < 8; i++) {
            __half2 a1 = __hfma2(y[j], w1[i * 9 + 8], b1[i]);
#pragma unroll
            for (int k = 0; k < 8; k++) a1 = __hfma2(flow[k], w1[i * 9 + k], a1);
            acc[i] = a1;
        }
#pragma unroll
        for (int i = 0; i < 8; i++) flow[i] = tanh_h2(acc[i]);
    }

    // widen flow to f32x2 for the f2 stack (8 cvt pairs)
    u64 flowf[8];
#pragma unroll
    for (int i = 0; i < 8; i++) flowf[i] = h2_to_f2(flow[i]);

    // ---- f2 layer 0: tanh(flow @ W20^T + b20' + tau * sp(Wtau)^T) ----
    u64 taup;
    {
        float2 tv = *(const float2*)(tau + r0);
        taup = pack2(tv.x, tv.y);
    }
    u64 g[8];
#pragma unroll
    for (int i = 0; i < 8; i++) {
        u64 a1 = sB20[i];
        a1 = ffma2(taup, sTW[i], a1);
#pragma unroll
        for (int k = 0; k < 8; k++) a1 = ffma2(flowf[k], sW20[i * 8 + k], a1);
        g[i] = tanh2_f(a1);
    }

    // ---- f2 layer 1: tanh(g @ sp(W21)^T + sp(b21)) ----
    u64 h[8];
#pragma unroll
    for (int i = 0; i < 8; i++) {
        u64 a1 = sB21[i];
#pragma unroll
        for (int k = 0; k < 8; k++) a1 = ffma2(g[k], sW21[i * 8 + k], a1);
        h[i] = tanh2_f(a1);
    }

    // ---- output: softplus(h @ sp(W22)^T + sp(b22)) ----
    u64 o = sB22;
#pragma unroll
    for (int k = 0; k < 8; k++) o = ffma2(h[k], sW22[k], o);

    float o0, o1; unpack2(o, o0, o1);
    float2 res;
    res.x = softplus_out(o0);
    res.y = softplus_out(o1);
    *(float2*)(out + r0) = res;
}

extern "C" void kernel_launch(void* const* d_in, const int* in_sizes, int n_in,
                              void* d_out, int out_size)
{
    const float* Y    = (const float*)d_in[0];
    const float* tau  = (const float*)d_in[1];
    const float* f1W  = (const float*)d_in[2];
    const float* f1b  = (const float*)d_in[3];
    const float* ftW  = (const float*)d_in[4];
    const float* ftb  = (const float*)d_in[5];
    const float* f20W = (const float*)d_in[6];
    const float* f20b = (const float*)d_in[7];
    const float* f21W = (const float*)d_in[8];
    const float* f21b = (const float*)d_in[9];
    const float* f22W = (const float*)d_in[10];
    const float* f22b = (const float*)d_in[11];
    float* out = (float*)d_out;

    int npairs = out_size / 2;  // 2M threads, 2 rows each
    int blocks = (npairs + NTHREADS - 1) / NTHREADS;
    hazard_kernel<<<blocks, NTHREADS>>>(Y, tau, f1W, f1b, ftW, ftb,
                                        f20W, f20b, f21W, f21b, f22W, f22b,
                                        out, npairs);
}

// round 9
// speedup vs baseline: 3.4172x; 1.2785x over previous
#include <cuda_runtime.h>
#include <cuda_fp16.h>

// cumulative_hazard R8: tensor-core formulation.
// Each warp owns 64 rows as 4x m16n8 fragments. RNN step = mma.m16n8k16
// ([flow|y|0-pad] @ W1^T + bias-in-C), tanh.approx.f16x2 on the C fragment,
// which IS the next A fragment (identical layout). f2 layers 0/1 = mma.m16n8k8.
// Output layer = f32 dot + quad shfl reduce. y/tau staged in shared as
// (row g, row g+8) half2 pairs; writer warp == owner warp -> __syncwarp only.

typedef unsigned u32;

#define NTHREADS 256
#define ROWS_PER_BLOCK 512   // 8 warps x 64 rows

__device__ __forceinline__ u32 h2u(__half lo, __half hi) {
    __half2 v = __halves2half2(lo, hi);
    return *reinterpret_cast<u32*>(&v);
}
__device__ __forceinline__ u32 hfma2u(u32 a, u32 b, u32 c) {
    u32 d; asm("fma.rn.f16x2 %0, %1, %2, %3;" : "=r"(d) : "r"(a), "r"(b), "r"(c));
    return d;
}
__device__ __forceinline__ u32 tanh_u(u32 v) {
    asm("tanh.approx.f16x2 %0, %0;" : "+r"(v));
    return v;
}
__device__ __forceinline__ void mma16816(u32& c0, u32& c1,
                                         u32 a0, u32 a1, u32 a2, u32 a3,
                                         u32 b0, u32 b1) {
    asm("mma.sync.aligned.m16n8k16.row.col.f16.f16.f16.f16 "
        "{%0,%1}, {%2,%3,%4,%5}, {%6,%7}, {%0,%1};"
        : "+r"(c0), "+r"(c1)
        : "r"(a0), "r"(a1), "r"(a2), "r"(a3), "r"(b0), "r"(b1));
}
__device__ __forceinline__ void mma1688(u32& c0, u32& c1,
                                        u32 a0, u32 a1, u32 b0) {
    asm("mma.sync.aligned.m16n8k8.row.col.f16.f16.f16.f16 "
        "{%0,%1}, {%2,%3}, {%4}, {%0,%1};"
        : "+r"(c0), "+r"(c1)
        : "r"(a0), "r"(a1), "r"(b0));
}

__device__ __forceinline__ float softplus_out(float x) {
    float ax = fabsf(x);
    float l = log1pf(__expf(-ax));
    return x > 0.0f ? x + l : l;
}
__device__ __forceinline__ float sp_precise(float x) {
    float ax = fabsf(x);
    float l = log1pf(expf(-ax));
    return x > 0.0f ? x + l : l;
}

__global__ __launch_bounds__(NTHREADS)
void hazard_kernel(const float* __restrict__ Y,     // [N,16]
                   const float* __restrict__ tau,   // [N,1]
                   const float* __restrict__ f1W,   // [8,9]
                   const float* __restrict__ f1b,   // [8]
                   const float* __restrict__ ftW,   // [8,1]
                   const float* __restrict__ ftb,   // [8]
                   const float* __restrict__ f20W,  // [8,8]
                   const float* __restrict__ f20b,  // [8]
                   const float* __restrict__ f21W,  // [8,8]
                   const float* __restrict__ f21b,  // [8]
                   const float* __restrict__ f22W,  // [1,8]
                   const float* __restrict__ f22b,  // [1]
                   float* __restrict__ out,         // [N]
                   int N)
{
    __shared__ __half sW1[72], sB1[8];
    __shared__ __half sW20[64], sB20[8], sTW[8];
    __shared__ __half sW21[64], sB21[8];
    __shared__ float  sW22f[8];
    __shared__ float  sB22f;
    // y: [warp][tile][g][j] as half2(row g, row g+8);  tau: [warp][tile][g]
    __shared__ u32 sY[8 * 4 * 8 * 11];
    __shared__ u32 sTau[8 * 4 * 8];

    const int t = threadIdx.x;
    // ---- weight preprocessing (softplus folded; f16) ----
    if (t < 72)        { sW1[t] = __float2half(f1W[t]); }
    else if (t < 80)   { int i = t - 72;  sB1[i]  = __float2half(f1b[i]); }
    else if (t < 144)  { int i = t - 80;  sW20[i] = __float2half(f20W[i]); }
    else if (t < 152)  { int i = t - 144; sB20[i] = __float2half(f20b[i] + sp_precise(ftb[i])); }
    else if (t < 160)  { int i = t - 152; sTW[i]  = __float2half(sp_precise(ftW[i])); }
    else if (t < 224)  { int i = t - 160; sW21[i] = __float2half(sp_precise(f21W[i])); }
    else if (t < 232)  { int i = t - 224; sB21[i] = __float2half(sp_precise(f21b[i])); }
    else if (t < 240)  { int i = t - 232; sW22f[i] = sp_precise(f22W[i]); }
    else if (t == 240) { sB22f = sp_precise(f22b[0]); }
    __syncthreads();

    const int lane = t & 31;
    const int warp = t >> 5;
    const int g  = lane >> 2;   // 0..7  (fragment row within half-tile / col n)
    const int tq = lane & 3;    // 0..3  (fragment col group / k group)

    const long long base = (long long)blockIdx.x * ROWS_PER_BLOCK;

    // ---- load 2 rows, compute log-gaps, stage y & tau into shared ----
    {
        const int rp = 2 * t;                       // local rows rp, rp+1
        long long r0 = base + rp;
        if (r0 > (long long)N - 2) r0 = (long long)N - 2;   // clamp (dup rows, stores predicated)

        const float4* yp = (const float4*)(Y + r0 * 16);
        float4 q0 = yp[0], q1 = yp[1], q2 = yp[2], q3 = yp[3];
        float4 p0 = yp[4], p1 = yp[5], p2 = yp[6], p3 = yp[7];
        float ra[16] = { q0.x,q0.y,q0.z,q0.w, q1.x,q1.y,q1.z,q1.w,
                         q2.x,q2.y,q2.z,q2.w, q3.x,q3.y,q3.z,q3.w };
        float rb[16] = { p0.x,p0.y,p0.z,p0.w, p1.x,p1.y,p1.z,p1.w,
                         p2.x,p2.y,p2.z,p2.w, p3.x,p3.y,p3.z,p3.w };

        __half* yh = reinterpret_cast<__half*>(sY);
        __half* th = reinterpret_cast<__half*>(sTau);

        // both rows rp, rp+1 share (warp, tile, half); g = even/odd pair
        const int tile = (rp >> 4) & 3;
        const int hs   = (rp >> 3) & 1;
        const int g0   = rp & 7;          // even
#pragma unroll
        for (int j = 0; j < 11; j++) {
            float d0 = __logf(ra[4 + j] - ra[3 + j] + 0.1f);
            float d1 = __logf(rb[4 + j] - rb[3 + j] + 0.1f);
            int i0 = (((warp * 4 + tile) * 8 + g0)     * 11 + j) * 2 + hs;
            int i1 = (((warp * 4 + tile) * 8 + g0 + 1) * 11 + j) * 2 + hs;
            yh[i0] = __float2half(d0);
            yh[i1] = __float2half(d1);
        }
        float2 tv = *(const float2*)(tau + r0);
        th[((warp * 4 + tile) * 8 + g0)     * 2 + hs] = __float2half(tv.x);
        th[((warp * 4 + tile) * 8 + g0 + 1) * 2 + hs] = __float2half(tv.y);
    }
    __syncwarp();   // writer warp == owner warp for all staged data

    // ---- per-thread fragment weights ----
    const u32 w1b0 = h2u(sW1[g * 9 + 2 * tq], sW1[g * 9 + 2 * tq + 1]);
    const u32 w1b1 = (tq == 0) ? h2u(sW1[g * 9 + 8], __float2half(0.0f)) : 0u;
    const u32 bc1  = h2u(sB1[2 * tq], sB1[2 * tq + 1]);
    const u32 w20b = h2u(sW20[g * 8 + 2 * tq], sW20[g * 8 + 2 * tq + 1]);
    const u32 b20p = h2u(sB20[2 * tq], sB20[2 * tq + 1]);
    const u32 tWp  = h2u(sTW[2 * tq], sTW[2 * tq + 1]);
    const u32 w21b = h2u(sW21[g * 8 + 2 * tq], sW21[g * 8 + 2 * tq + 1]);
    const u32 b21p = h2u(sB21[2 * tq], sB21[2 * tq + 1]);
    const float w22a = sW22f[2 * tq], w22c = sW22f[2 * tq + 1];
    const float b22  = sB22f;
    const u32 ymask = (tq == 0) ? 0xFFFFFFFFu : 0u;

    const u32* yW = sY + (warp * 4) * 8 * 11;   // this warp's y block
    const u32* tW2 = sTau + (warp * 4) * 8;

    // ---- RNN: 4 fragments (64 rows), 11 mma steps ----
    u32 f0[4] = {0u, 0u, 0u, 0u};    // C/A fragment reg0: rows g,   cols 2tq,2tq+1
    u32 f1r[4] = {0u, 0u, 0u, 0u};   // reg1: rows g+8

#pragma unroll
    for (int j = 0; j < 11; j++) {
#pragma unroll
        for (int tile = 0; tile < 4; tile++) {
            u32 yp = yW[(tile * 8 + g) * 11 + j] & ymask;  // broadcast LDS + mask
            u32 a45 = yp & 0xFFFFu;        // (y row g,   0)  col 8,9
            u32 a67 = yp >> 16;            // (y row g+8, 0)
            u32 c0 = bc1, c1 = bc1;
            mma16816(c0, c1, f0[tile], f1r[tile], a45, a67, w1b0, w1b1);
            f0[tile]  = tanh_u(c0);
            f1r[tile] = tanh_u(c1);
        }
    }

    // ---- f2 layer 0: tanh(flow @ W20^T + b20' + tau*sp(Wtau)) ----
#pragma unroll
    for (int tile = 0; tile < 4; tile++) {
        u32 tp = tW2[tile * 8 + g];
        u32 tlo = (tp & 0xFFFFu); tlo |= (tlo << 16);   // splat tau(row g)
        u32 thi = (tp >> 16);     thi |= (thi << 16);   // splat tau(row g+8)
        u32 c0 = hfma2u(tlo, tWp, b20p);
        u32 c1 = hfma2u(thi, tWp, b20p);
        mma1688(c0, c1, f0[tile], f1r[tile], w20b);
        f0[tile]  = tanh_u(c0);
        f1r[tile] = tanh_u(c1);
    }

    // ---- f2 layer 1: tanh(g @ sp(W21)^T + sp(b21)) ----
#pragma unroll
    for (int tile = 0; tile < 4; tile++) {
        u32 c0 = b21p, c1 = b21p;
        mma1688(c0, c1, f0[tile], f1r[tile], w21b);
        f0[tile]  = tanh_u(c0);
        f1r[tile] = tanh_u(c1);
    }

    // ---- output layer: f32 dot over 8 cols (quad-distributed) + shfl reduce ----
#pragma unroll
    for (int tile = 0; tile < 4; tile++) {
        __half2 hA = *reinterpret_cast<__half2*>(&f0[tile]);   // row g:   cols 2tq,2tq+1
        __half2 hB = *reinterpret_cast<__half2*>(&f1r[tile]);  // row g+8
        float2 fa = __half22float2(hA);
        float2 fb = __half22float2(hB);
        float pl = fa.x * w22a + fa.y * w22c;
        float ph = fb.x * w22a + fb.y * w22c;
        pl += __shfl_xor_sync(0xFFFFFFFFu, pl, 1);
        pl += __shfl_xor_sync(0xFFFFFFFFu, pl, 2);
        ph += __shfl_xor_sync(0xFFFFFFFFu, ph, 1);
        ph += __shfl_xor_sync(0xFFFFFFFFu, ph, 2);
        if (tq == 0) {
            long long rlo = base + warp * 64 + tile * 16 + g;
            long long rhi = rlo + 8;
            if (rlo < N) out[rlo] = softplus_out(pl + b22);
            if (rhi < N) out[rhi] = softplus_out(ph + b22);
        }
    }
}

extern "C" void kernel_launch(void* const* d_in, const int* in_sizes, int n_in,
                              void* d_out, int out_size)
{
    const float* Y    = (const float*)d_in[0];
    const float* tau  = (const float*)d_in[1];
    const float* f1W  = (const float*)d_in[2];
    const float* f1b  = (const float*)d_in[3];
    const float* ftW  = (const float*)d_in[4];
    const float* ftb  = (const float*)d_in[5];
    const float* f20W = (const float*)d_in[6];
    const float* f20b = (const float*)d_in[7];
    const float* f21W = (const float*)d_in[8];
    const float* f21b = (const float*)d_in[9];
    const float* f22W = (const float*)d_in[10];
    const float* f22b = (const float*)d_in[11];
    float* out = (float*)d_out;

    int N = out_size;
    int blocks = (N + ROWS_PER_BLOCK - 1) / ROWS_PER_BLOCK;
    hazard_kernel<<<blocks, NTHREADS>>>(Y, tau, f1W, f1b, ftW, ftb,
                                        f20W, f20b, f21W, f21b, f22W, f22b,
                                        out, N);
}